// round 1
// baseline (speedup 1.0000x reference)
#include <cuda_runtime.h>

#define EMBED 1024
#define HEAD  128
#define BATCH 4
#define SEQ   4096
#define BS    (BATCH*SEQ)
#define SCALE 0.03125f   // 1/sqrt(1024)

// scratch for projected q,k,v (device globals: no allocation allowed)
__device__ float g_q[BS*HEAD];
__device__ float g_k[BS*HEAD];
__device__ float g_v[BS*HEAD];

// ---------------------------------------------------------------------------
// Projection GEMM: [16384,1024] x [1024,128] -> [16384,128], one weight per
// blockIdx.y. 64x128 block tile, 256 threads, 4x8 register tile per thread.
// x tile stored transposed (xT[kk][row], pad 68) and W tile padded (132) so the
// inner loop is 3 LDS.128 per 32 FMAs -> FMA-bound.
// ---------------------------------------------------------------------------
__global__ __launch_bounds__(256) void proj_kernel(
    const float* __restrict__ x,
    const float* __restrict__ Wk,
    const float* __restrict__ Wq,
    const float* __restrict__ Wv)
{
    __shared__ float xT[32*68];    // [d=0..31][row=0..63], pad 68
    __shared__ float ws[32*132];   // [d=0..31][col=0..127], pad 132

    const int tid = threadIdx.x;
    const int rg  = tid >> 4;      // 0..15 (row group: 4 rows)
    const int cg  = tid & 15;      // 0..15 (col group: 8 cols)
    const int w   = blockIdx.y;
    const float* W   = (w == 0) ? Wq : (w == 1) ? Wk : Wv;
    float*       out = (w == 0) ? g_q : (w == 1) ? g_k : g_v;
    const int row0 = blockIdx.x * 64;

    float acc[4][8];
    #pragma unroll
    for (int i = 0; i < 4; i++)
        #pragma unroll
        for (int j = 0; j < 8; j++) acc[i][j] = 0.f;

    for (int k0 = 0; k0 < EMBED; k0 += 32) {
        __syncthreads();
        // x tile [64 rows][32 k] -> transposed xT (coalesced global read over d)
        #pragma unroll
        for (int i = 0; i < 8; i++) {
            int f = i*256 + tid;
            int r = f >> 5, d = f & 31;
            xT[d*68 + r] = x[(size_t)(row0 + r)*EMBED + k0 + d];
        }
        // W tile [32 k][128 cols]
        #pragma unroll
        for (int i = 0; i < 4; i++) {
            int f4 = i*256 + tid;
            int r = f4 >> 5, c4 = (f4 & 31) << 2;
            *(float4*)&ws[r*132 + c4] = *(const float4*)&W[(size_t)(k0 + r)*HEAD + c4];
        }
        __syncthreads();

        #pragma unroll
        for (int kk = 0; kk < 32; kk++) {
            float4 a  = *(float4*)&xT[kk*68 + rg*4];
            float4 b0 = *(float4*)&ws[kk*132 + cg*8];
            float4 b1 = *(float4*)&ws[kk*132 + cg*8 + 4];
            float av[4] = {a.x, a.y, a.z, a.w};
            float bv[8] = {b0.x, b0.y, b0.z, b0.w, b1.x, b1.y, b1.z, b1.w};
            #pragma unroll
            for (int i = 0; i < 4; i++)
                #pragma unroll
                for (int j = 0; j < 8; j++)
                    acc[i][j] = fmaf(av[i], bv[j], acc[i][j]);
        }
    }

    #pragma unroll
    for (int i = 0; i < 4; i++) {
        size_t r = (size_t)(row0 + rg*4 + i);
        float4 o0 = {acc[i][0], acc[i][1], acc[i][2], acc[i][3]};
        float4 o1 = {acc[i][4], acc[i][5], acc[i][6], acc[i][7]};
        *(float4*)&out[r*HEAD + cg*8]     = o0;
        *(float4*)&out[r*HEAD + cg*8 + 4] = o1;
    }
}

// ---------------------------------------------------------------------------
// Flash attention: one block = one (batch, 64-query tile). Online softmax,
// O/m/l in registers. Q,K stored transposed in smem (pad 68) so score phase is
// 2 LDS.128 / 16 FMA; P stored transposed so PV phase is 3 LDS.128 / 32 FMA.
// ---------------------------------------------------------------------------
#define QT_OFF 0
#define KT_OFF (128*68)
#define VS_OFF (2*128*68)
#define PT_OFF (2*128*68 + 64*132)
#define SMEM_FLOATS (2*128*68 + 64*132 + 64*68)   // 30208 floats = 120832 B

__global__ __launch_bounds__(256) void attn_kernel(float* __restrict__ out)
{
    extern __shared__ float sm[];
    float* qT = sm + QT_OFF;   // [128][68] transposed
    float* kT = sm + KT_OFF;   // [128][68] transposed
    float* vs = sm + VS_OFF;   // [64][132] row-major
    float* pT = sm + PT_OFF;   // [64][68]  transposed (key-major)

    const int tid = threadIdx.x;
    const int rg  = tid >> 4;   // 0..15 (4 query rows each)
    const int cg  = tid & 15;   // 0..15
    const int b   = blockIdx.y;
    const int qt  = gridDim.x - 1 - blockIdx.x;   // heavy blocks first
    const int q0  = qt * 64;

    const float* qg = g_q + ((size_t)b*SEQ + q0)*HEAD;

    // load Q transposed (coalesced over d, stride-68 STS: conflict-light)
    #pragma unroll
    for (int i = 0; i < 32; i++) {
        int f = i*256 + tid;
        int r = f >> 7, d = f & 127;
        qT[d*68 + r] = qg[(size_t)r*HEAD + d];
    }

    float o[4][8];
    float m[4], l[4];
    #pragma unroll
    for (int i = 0; i < 4; i++) {
        m[i] = -1e30f; l[i] = 0.f;
        #pragma unroll
        for (int j = 0; j < 8; j++) o[i][j] = 0.f;
    }

    for (int kt = 0; kt <= qt; kt++) {
        __syncthreads();   // prev PV done; qT ready on first iter
        const float* kg = g_k + ((size_t)b*SEQ + kt*64)*HEAD;
        const float* vg = g_v + ((size_t)b*SEQ + kt*64)*HEAD;
        #pragma unroll
        for (int i = 0; i < 32; i++) {
            int f = i*256 + tid;
            int c = f >> 7, d = f & 127;
            kT[d*68 + c] = kg[(size_t)c*HEAD + d];
        }
        #pragma unroll
        for (int i = 0; i < 8; i++) {
            int f4 = i*256 + tid;
            int c = f4 >> 5, d4 = (f4 & 31) << 2;
            *(float4*)&vs[c*132 + d4] = *(const float4*)&vg[(size_t)c*HEAD + d4];
        }
        __syncthreads();

        // ---- scores: s[4 rows][4 cols] over 128 dims ----
        float s[4][4];
        #pragma unroll
        for (int i = 0; i < 4; i++)
            #pragma unroll
            for (int j = 0; j < 4; j++) s[i][j] = 0.f;

        #pragma unroll 4
        for (int d = 0; d < 128; d++) {
            float4 a  = *(float4*)&qT[d*68 + rg*4];
            float4 bb = *(float4*)&kT[d*68 + cg*4];
            float av[4] = {a.x, a.y, a.z, a.w};
            float bv[4] = {bb.x, bb.y, bb.z, bb.w};
            #pragma unroll
            for (int i = 0; i < 4; i++)
                #pragma unroll
                for (int j = 0; j < 4; j++)
                    s[i][j] = fmaf(av[i], bv[j], s[i][j]);
        }

        // ---- scale + causal mask (only diagonal tile can mask) ----
        const bool diag = (kt == qt);
        float tm[4];
        #pragma unroll
        for (int i = 0; i < 4; i++) {
            int qi = q0 + rg*4 + i;
            tm[i] = -1e30f;
            #pragma unroll
            for (int j = 0; j < 4; j++) {
                int kj = kt*64 + cg*4 + j;
                float v = s[i][j] * SCALE;
                if (diag && kj > qi) v = -1e30f;
                s[i][j] = v;
                tm[i] = fmaxf(tm[i], v);
            }
        }
        // row max across the 16 lanes owning this row's 64 key-cols
        #pragma unroll
        for (int i = 0; i < 4; i++) {
            #pragma unroll
            for (int off = 1; off < 16; off <<= 1)
                tm[i] = fmaxf(tm[i], __shfl_xor_sync(0xffffffffu, tm[i], off));
        }

        float corr[4], rs[4];
        #pragma unroll
        for (int i = 0; i < 4; i++) {
            float mn = fmaxf(m[i], tm[i]);
            corr[i] = __expf(m[i] - mn);
            m[i] = mn;
            rs[i] = 0.f;
            #pragma unroll
            for (int j = 0; j < 4; j++) {
                s[i][j] = __expf(s[i][j] - mn);
                rs[i] += s[i][j];
            }
        }
        #pragma unroll
        for (int i = 0; i < 4; i++) {
            #pragma unroll
            for (int off = 1; off < 16; off <<= 1)
                rs[i] += __shfl_xor_sync(0xffffffffu, rs[i], off);
            l[i] = l[i]*corr[i] + rs[i];
            #pragma unroll
            for (int j = 0; j < 8; j++) o[i][j] *= corr[i];
        }

        // write P transposed: pT[key][query-row]
        #pragma unroll
        for (int j = 0; j < 4; j++) {
            float4 pv = {s[0][j], s[1][j], s[2][j], s[3][j]};
            *(float4*)&pT[(cg*4 + j)*68 + rg*4] = pv;
        }
        __syncthreads();

        // ---- PV: o[4][8] += P[4 rows][64 keys] * V[64 keys][8 cols] ----
        #pragma unroll 2
        for (int c = 0; c < 64; c++) {
            float4 p4 = *(float4*)&pT[c*68 + rg*4];
            float4 v0 = *(float4*)&vs[c*132 + cg*8];
            float4 v1 = *(float4*)&vs[c*132 + cg*8 + 4];
            float pv[4] = {p4.x, p4.y, p4.z, p4.w};
            float vv[8] = {v0.x, v0.y, v0.z, v0.w, v1.x, v1.y, v1.z, v1.w};
            #pragma unroll
            for (int i = 0; i < 4; i++)
                #pragma unroll
                for (int j = 0; j < 8; j++)
                    o[i][j] = fmaf(pv[i], vv[j], o[i][j]);
        }
    }

    // epilogue: normalize and store
    #pragma unroll
    for (int i = 0; i < 4; i++) {
        float inv = 1.f / l[i];
        size_t r = (size_t)b*SEQ + q0 + rg*4 + i;
        float4 o0 = {o[i][0]*inv, o[i][1]*inv, o[i][2]*inv, o[i][3]*inv};
        float4 o1 = {o[i][4]*inv, o[i][5]*inv, o[i][6]*inv, o[i][7]*inv};
        *(float4*)&out[r*HEAD + cg*8]     = o0;
        *(float4*)&out[r*HEAD + cg*8 + 4] = o1;
    }
}

extern "C" void kernel_launch(void* const* d_in, const int* in_sizes, int n_in,
                              void* d_out, int out_size)
{
    const float* x  = (const float*)d_in[0];
    const float* Wk = (const float*)d_in[1];
    const float* Wq = (const float*)d_in[2];
    const float* Wv = (const float*)d_in[3];
    float* out = (float*)d_out;

    cudaFuncSetAttribute(attn_kernel, cudaFuncAttributeMaxDynamicSharedMemorySize,
                         SMEM_FLOATS * (int)sizeof(float));

    proj_kernel<<<dim3(BS/64, 3), 256>>>(x, Wk, Wq, Wv);
    attn_kernel<<<dim3(SEQ/64, BATCH), 256, SMEM_FLOATS * sizeof(float)>>>(out);
}

// round 3
// speedup vs baseline: 4.4350x; 4.4350x over previous
#include <cuda_runtime.h>
#include <cuda_bf16.h>
#include <cstdint>

#define EMBED 1024
#define HEAD  128
#define BATCH 4
#define SEQ   4096
#define BS    (BATCH*SEQ)
#define SCALE 0.03125f   // 1/sqrt(1024)

// ---------------------------------------------------------------------------
// Global scratch (bf16 hi/lo splits). No transposes needed anywhere.
// ---------------------------------------------------------------------------
__device__ __align__(256) __nv_bfloat16 g_xh[BS*EMBED], g_xl[BS*EMBED];
__device__ __align__(256) __nv_bfloat16 g_wh[3*EMBED*HEAD], g_wl[3*EMBED*HEAD];
__device__ __align__(256) __nv_bfloat16 g_qh[BS*HEAD], g_ql[BS*HEAD];
__device__ __align__(256) __nv_bfloat16 g_kh[BS*HEAD], g_kl[BS*HEAD];
__device__ __align__(256) __nv_bfloat16 g_vh[BS*HEAD], g_vl[BS*HEAD];

// ---------------------------------------------------------------------------
// helpers
// ---------------------------------------------------------------------------
__device__ __forceinline__ uint32_t smem_u32(const void* p) {
    uint32_t a;
    asm("{ .reg .u64 t; cvta.to.shared.u64 t, %1; cvt.u32.u64 %0, t; }" : "=r"(a) : "l"(p));
    return a;
}
// swizzled byte offset inside a tile with row stride rb bytes (rb = 128 or 256)
__device__ __forceinline__ uint32_t sidx(int row, int cb, int rb) {
    return (uint32_t)(row*rb + ((((cb >> 4) ^ (row & 7)) << 4) | (cb & 15)));
}
__device__ __forceinline__ void cpa(uint32_t d, const void* s) {
    asm volatile("cp.async.cg.shared.global [%0], [%1], 16;" :: "r"(d), "l"(s));
}
#define CP_COMMIT() asm volatile("cp.async.commit_group;" ::: "memory")
#define CP_WAIT0()  asm volatile("cp.async.wait_group 0;" ::: "memory")
#define CP_WAIT1()  asm volatile("cp.async.wait_group 1;" ::: "memory")

__device__ __forceinline__ void ldsm4(uint32_t* r, uint32_t a) {
    asm volatile("ldmatrix.sync.aligned.m8n8.x4.shared.b16 {%0,%1,%2,%3}, [%4];"
        : "=r"(r[0]), "=r"(r[1]), "=r"(r[2]), "=r"(r[3]) : "r"(a));
}
__device__ __forceinline__ void ldsm2(uint32_t* r, uint32_t a) {
    asm volatile("ldmatrix.sync.aligned.m8n8.x2.shared.b16 {%0,%1}, [%2];"
        : "=r"(r[0]), "=r"(r[1]) : "r"(a));
}
__device__ __forceinline__ void ldsm2t(uint32_t* r, uint32_t a) {
    asm volatile("ldmatrix.sync.aligned.m8n8.x2.trans.shared.b16 {%0,%1}, [%2];"
        : "=r"(r[0]), "=r"(r[1]) : "r"(a));
}
__device__ __forceinline__ void mma16816(float* d, const uint32_t* a, const uint32_t* b) {
    asm volatile("mma.sync.aligned.m16n8k16.row.col.f32.bf16.bf16.f32 "
        "{%0,%1,%2,%3}, {%4,%5,%6,%7}, {%8,%9}, {%0,%1,%2,%3};"
        : "+f"(d[0]), "+f"(d[1]), "+f"(d[2]), "+f"(d[3])
        : "r"(a[0]), "r"(a[1]), "r"(a[2]), "r"(a[3]), "r"(b[0]), "r"(b[1]));
}
__device__ __forceinline__ void split2(float a, float b, uint32_t& hi, uint32_t& lo) {
    __nv_bfloat162 h = __float22bfloat162_rn(make_float2(a, b));
    float2 hf = __bfloat1622float2(h);
    __nv_bfloat162 l = __float22bfloat162_rn(make_float2(a - hf.x, b - hf.y));
    hi = *(uint32_t*)&h; lo = *(uint32_t*)&l;
}

// ---------------------------------------------------------------------------
// convert kernels: fp32 -> bf16 hi/lo
// ---------------------------------------------------------------------------
__global__ __launch_bounds__(256) void conv_x_kernel(const float* __restrict__ x)
{
    size_t i = ((size_t)blockIdx.x*256 + threadIdx.x)*4;
    float4 v = *(const float4*)(x + i);
    uint32_t h0, l0, h1, l1;
    split2(v.x, v.y, h0, l0);
    split2(v.z, v.w, h1, l1);
    *(uint2*)(g_xh + i) = make_uint2(h0, h1);
    *(uint2*)(g_xl + i) = make_uint2(l0, l1);
}
__global__ __launch_bounds__(256) void conv_w_kernel(
    const float* __restrict__ Wk, const float* __restrict__ Wq, const float* __restrict__ Wv)
{
    const int w = blockIdx.y;
    const float* W = (w == 0) ? Wq : (w == 1) ? Wk : Wv;
    size_t base = (size_t)w*EMBED*HEAD;
    size_t i = ((size_t)blockIdx.x*256 + threadIdx.x)*4;
    float4 v = *(const float4*)(W + i);
    uint32_t h0, l0, h1, l1;
    split2(v.x, v.y, h0, l0);
    split2(v.z, v.w, h1, l1);
    *(uint2*)(g_wh + base + i) = make_uint2(h0, h1);
    *(uint2*)(g_wl + base + i) = make_uint2(l0, l1);
}

// ---------------------------------------------------------------------------
// Projection GEMM on HMMA: [16384,1024]x[1024,128], split-bf16 (3 passes).
// CTA: 128 rows, 8 warps (16 rows each), K chunks of 64, cp.async double-buf.
// smem/stage: XH 16K | XL 16K | WH 16K | WL 16K  (2 stages = 128KB)
// ---------------------------------------------------------------------------
#define PJ_STAGE 65536
#define PJ_SMEM  (2*PJ_STAGE)

__global__ __launch_bounds__(256, 1) void proj_kernel()
{
    extern __shared__ char sm[];
    const uint32_t smb = smem_u32(sm);
    const int tid = threadIdx.x, wid = tid >> 5, l = tid & 31;
    const int w = blockIdx.y;
    const int row0 = blockIdx.x * 128;

    const __nv_bfloat16* xh = g_xh + (size_t)row0*EMBED;
    const __nv_bfloat16* xl = g_xl + (size_t)row0*EMBED;
    const __nv_bfloat16* wh = g_wh + (size_t)w*EMBED*HEAD;
    const __nv_bfloat16* wl = g_wl + (size_t)w*EMBED*HEAD;

    auto load_stage = [&](int s, int k0) {
        uint32_t sb = smb + s*PJ_STAGE;
        #pragma unroll
        for (int i = 0; i < 4; i++) {             // x tiles [128][64]
            int f = i*256 + tid;
            int r = f >> 3, c = f & 7;
            uint32_t d = sb + sidx(r, c*16, 128);
            cpa(d,         xh + (size_t)r*EMBED + k0 + c*8);
            cpa(d + 16384, xl + (size_t)r*EMBED + k0 + c*8);
        }
        #pragma unroll
        for (int i = 0; i < 4; i++) {             // W tiles [64][128]
            int f = i*256 + tid;
            int r = f >> 4, c = f & 15;
            uint32_t d = sb + 32768 + sidx(r, c*16, 256);
            cpa(d,         wh + (size_t)(k0 + r)*HEAD + c*8);
            cpa(d + 16384, wl + (size_t)(k0 + r)*HEAD + c*8);
        }
        CP_COMMIT();
    };

    float acc[16][4];
    #pragma unroll
    for (int n = 0; n < 16; n++)
        #pragma unroll
        for (int j = 0; j < 4; j++) acc[n][j] = 0.f;

    load_stage(0, 0);
    const int rb = wid*16;

    for (int ch = 0; ch < 16; ch++) {
        int cur = ch & 1;
        if (ch + 1 < 16) { load_stage(cur ^ 1, (ch + 1)*64); CP_WAIT1(); }
        else             { CP_WAIT0(); }
        __syncthreads();

        uint32_t sb = smb + cur*PJ_STAGE;
        #pragma unroll
        for (int ks = 0; ks < 4; ks++) {
            uint32_t ah[4], al[4];
            uint32_t aoff = sidx(rb + (l & 15), ks*32 + ((l >> 4) << 4), 128);
            ldsm4(ah, sb + aoff);
            ldsm4(al, sb + 16384 + aoff);
            #pragma unroll
            for (int nt = 0; nt < 16; nt++) {
                uint32_t bh[2], bl2[2];
                uint32_t boff = sidx(ks*16 + (l & 15), nt*16, 256);
                ldsm2t(bh,  sb + 32768 + boff);
                ldsm2t(bl2, sb + 49152 + boff);
                mma16816(acc[nt], ah, bh);
                mma16816(acc[nt], ah, bl2);
                mma16816(acc[nt], al, bh);
            }
        }
        __syncthreads();
    }

    __nv_bfloat16* dh = (w == 0) ? g_qh : (w == 1) ? g_kh : g_vh;
    __nv_bfloat16* dl = (w == 0) ? g_ql : (w == 1) ? g_kl : g_vl;
    const int g0 = row0 + rb + (l >> 2);
    const int cb = (l & 3)*2;
    #pragma unroll
    for (int nt = 0; nt < 16; nt++) {
        uint32_t h, lo;
        split2(acc[nt][0], acc[nt][1], h, lo);
        *(uint32_t*)(dh + (size_t)g0*HEAD + nt*8 + cb) = h;
        *(uint32_t*)(dl + (size_t)g0*HEAD + nt*8 + cb) = lo;
        split2(acc[nt][2], acc[nt][3], h, lo);
        *(uint32_t*)(dh + (size_t)(g0 + 8)*HEAD + nt*8 + cb) = h;
        *(uint32_t*)(dl + (size_t)(g0 + 8)*HEAD + nt*8 + cb) = lo;
    }
}

// ---------------------------------------------------------------------------
// Flash attention on HMMA, split-bf16, no-max softmax, O in registers.
// CTA: 64 queries (4 warps x 16 rows), 64-key tiles double-buffered.
// smem: QH 16K | QL 16K | 2 x stage{KH,KL,VH,VL each 16K} = 160KB
// ---------------------------------------------------------------------------
#define AT_KV0   32768
#define AT_STAGE 65536
#define AT_SMEM  (AT_KV0 + 2*AT_STAGE)

__global__ __launch_bounds__(128, 1) void attn_kernel(float* __restrict__ out)
{
    extern __shared__ char sm[];
    const uint32_t smb = smem_u32(sm);
    const int tid = threadIdx.x, wid = tid >> 5, l = tid & 31;
    const int b  = blockIdx.y;
    const int qt = gridDim.x - 1 - blockIdx.x;    // heavy tiles first
    const int q0 = qt*64;
    const int n_kt = qt + 1;
    const int wq = wid*16;

    // Q tiles (persistent), via cp.async into group 0
    {
        const __nv_bfloat16* qh = g_qh + ((size_t)b*SEQ + q0)*HEAD;
        const __nv_bfloat16* ql = g_ql + ((size_t)b*SEQ + q0)*HEAD;
        #pragma unroll
        for (int i = 0; i < 8; i++) {
            int f = i*128 + tid;
            int r = f >> 4, c = f & 15;
            uint32_t d = smb + sidx(r, c*16, 256);
            cpa(d,         qh + (size_t)r*HEAD + c*8);
            cpa(d + 16384, ql + (size_t)r*HEAD + c*8);
        }
    }

    auto load_kv = [&](int s, int kt) {
        uint32_t sb = smb + AT_KV0 + s*AT_STAGE;
        const size_t base = ((size_t)b*SEQ + kt*64)*HEAD;
        #pragma unroll
        for (int i = 0; i < 8; i++) {
            int f = i*128 + tid;
            int r = f >> 4, c = f & 15;
            uint32_t d = sb + sidx(r, c*16, 256);
            const size_t g = base + (size_t)r*HEAD + c*8;
            cpa(d,         g_kh + g);
            cpa(d + 16384, g_kl + g);
            cpa(d + 32768, g_vh + g);
            cpa(d + 49152, g_vl + g);
        }
        CP_COMMIT();
    };

    float o[16][4];
    #pragma unroll
    for (int n = 0; n < 16; n++)
        #pragma unroll
        for (int j = 0; j < 4; j++) o[n][j] = 0.f;
    float lsum0 = 0.f, lsum1 = 0.f;

    load_kv(0, 0);   // commits Q loads too (group 0)

    for (int kt = 0; kt < n_kt; kt++) {
        int cur = kt & 1;
        if (kt + 1 < n_kt) { load_kv(cur ^ 1, kt + 1); CP_WAIT1(); }
        else               { CP_WAIT0(); }
        __syncthreads();

        uint32_t sb = smb + AT_KV0 + cur*AT_STAGE;

        // ---- scores S[16q x 64k] per warp ----
        float s[8][4];
        #pragma unroll
        for (int n = 0; n < 8; n++)
            #pragma unroll
            for (int j = 0; j < 4; j++) s[n][j] = 0.f;

        #pragma unroll
        for (int ks = 0; ks < 8; ks++) {
            uint32_t ah[4], al[4];
            uint32_t aoff = sidx(wq + (l & 15), ks*32 + ((l >> 4) << 4), 256);
            ldsm4(ah, smb + aoff);
            ldsm4(al, smb + 16384 + aoff);
            #pragma unroll
            for (int nt = 0; nt < 8; nt++) {
                uint32_t bh[2], bl2[2];
                uint32_t boff = sidx(nt*8 + (l & 7), ks*32 + ((l >> 3) & 1)*16, 256);
                ldsm2(bh,  sb + boff);
                ldsm2(bl2, sb + 16384 + boff);
                mma16816(s[nt], ah, bh);
                mma16816(s[nt], ah, bl2);
                mma16816(s[nt], al, bh);
            }
        }

        // ---- p = exp(s*scale), causal mask on diagonal tile, pack bf16 hi/lo ----
        uint32_t Ph[8][2], Pl[8][2];
        const bool diag = (kt == n_kt - 1);
        const int lq = wq + (l >> 2);
        #pragma unroll
        for (int nt = 0; nt < 8; nt++) {
            int kc = nt*8 + (l & 3)*2;
            float p00 = __expf(s[nt][0]*SCALE);
            float p01 = __expf(s[nt][1]*SCALE);
            float p10 = __expf(s[nt][2]*SCALE);
            float p11 = __expf(s[nt][3]*SCALE);
            if (diag) {
                if (kc     > lq)     p00 = 0.f;
                if (kc + 1 > lq)     p01 = 0.f;
                if (kc     > lq + 8) p10 = 0.f;
                if (kc + 1 > lq + 8) p11 = 0.f;
            }
            lsum0 += p00 + p01;
            lsum1 += p10 + p11;
            split2(p00, p01, Ph[nt][0], Pl[nt][0]);
            split2(p10, p11, Ph[nt][1], Pl[nt][1]);
        }

        // ---- O += P * V (V via ldmatrix.trans; P already A-fragment layout) ----
        #pragma unroll
        for (int ks = 0; ks < 4; ks++) {
            uint32_t ahh[4] = {Ph[2*ks][0], Ph[2*ks][1], Ph[2*ks+1][0], Ph[2*ks+1][1]};
            uint32_t all[4] = {Pl[2*ks][0], Pl[2*ks][1], Pl[2*ks+1][0], Pl[2*ks+1][1]};
            #pragma unroll
            for (int nt = 0; nt < 16; nt++) {
                uint32_t bh[2], bl2[2];
                uint32_t boff = sidx(ks*16 + (l & 15), nt*16, 256);
                ldsm2t(bh,  sb + 32768 + boff);
                ldsm2t(bl2, sb + 49152 + boff);
                mma16816(o[nt], ahh, bh);
                mma16816(o[nt], ahh, bl2);
                mma16816(o[nt], all, bh);
            }
        }
        __syncthreads();
    }

    // ---- normalize, store ----
    lsum0 += __shfl_xor_sync(0xffffffffu, lsum0, 1);
    lsum0 += __shfl_xor_sync(0xffffffffu, lsum0, 2);
    lsum1 += __shfl_xor_sync(0xffffffffu, lsum1, 1);
    lsum1 += __shfl_xor_sync(0xffffffffu, lsum1, 2);
    const float inv0 = 1.f / lsum0;
    const float inv1 = 1.f / lsum1;

    float* og = out + ((size_t)b*SEQ + q0 + wq + (l >> 2))*HEAD;
    const int cb = (l & 3)*2;
    #pragma unroll
    for (int nt = 0; nt < 16; nt++) {
        float2 v0 = {o[nt][0]*inv0, o[nt][1]*inv0};
        float2 v1 = {o[nt][2]*inv1, o[nt][3]*inv1};
        *(float2*)(og + nt*8 + cb) = v0;
        *(float2*)(og + (size_t)8*HEAD + nt*8 + cb) = v1;
    }
}

// ---------------------------------------------------------------------------
extern "C" void kernel_launch(void* const* d_in, const int* in_sizes, int n_in,
                              void* d_out, int out_size)
{
    const float* x  = (const float*)d_in[0];
    const float* Wk = (const float*)d_in[1];
    const float* Wq = (const float*)d_in[2];
    const float* Wv = (const float*)d_in[3];
    float* out = (float*)d_out;

    cudaFuncSetAttribute(proj_kernel, cudaFuncAttributeMaxDynamicSharedMemorySize, PJ_SMEM);
    cudaFuncSetAttribute(attn_kernel, cudaFuncAttributeMaxDynamicSharedMemorySize, AT_SMEM);

    conv_x_kernel<<<BS*EMBED/1024, 256>>>(x);
    conv_w_kernel<<<dim3(EMBED*HEAD/1024, 3), 256>>>(Wk, Wq, Wv);
    proj_kernel<<<dim3(BS/128, 3), 256, PJ_SMEM>>>();
    attn_kernel<<<dim3(SEQ/64, BATCH), 128, AT_SMEM>>>(out);
}

// round 4
// speedup vs baseline: 4.6943x; 1.0585x over previous
#include <cuda_runtime.h>
#include <cuda_bf16.h>
#include <cstdint>

#define EMBED 1024
#define HEAD  128
#define BATCH 4
#define SEQ   4096
#define BS    (BATCH*SEQ)
#define SCALE 0.03125f   // 1/sqrt(1024)

// ---------------------------------------------------------------------------
// Global scratch (bf16 hi/lo splits) + l accumulator
// ---------------------------------------------------------------------------
__device__ __align__(256) __nv_bfloat16 g_xh[BS*EMBED], g_xl[BS*EMBED];
__device__ __align__(256) __nv_bfloat16 g_wh[3*EMBED*HEAD], g_wl[3*EMBED*HEAD];
__device__ __align__(256) __nv_bfloat16 g_qh[BS*HEAD], g_ql[BS*HEAD];
__device__ __align__(256) __nv_bfloat16 g_kh[BS*HEAD], g_kl[BS*HEAD];
__device__ __align__(256) __nv_bfloat16 g_vh[BS*HEAD], g_vl[BS*HEAD];
__device__ __align__(256) float g_l[BS];

// ---------------------------------------------------------------------------
// helpers
// ---------------------------------------------------------------------------
__device__ __forceinline__ uint32_t smem_u32(const void* p) {
    uint32_t a;
    asm("{ .reg .u64 t; cvta.to.shared.u64 t, %1; cvt.u32.u64 %0, t; }" : "=r"(a) : "l"(p));
    return a;
}
__device__ __forceinline__ uint32_t sidx(int row, int cb, int rb) {
    return (uint32_t)(row*rb + ((((cb >> 4) ^ (row & 7)) << 4) | (cb & 15)));
}
__device__ __forceinline__ void cpa(uint32_t d, const void* s) {
    asm volatile("cp.async.cg.shared.global [%0], [%1], 16;" :: "r"(d), "l"(s));
}
#define CP_COMMIT() asm volatile("cp.async.commit_group;" ::: "memory")
#define CP_WAIT0()  asm volatile("cp.async.wait_group 0;" ::: "memory")
#define CP_WAIT1()  asm volatile("cp.async.wait_group 1;" ::: "memory")

__device__ __forceinline__ void ldsm4(uint32_t* r, uint32_t a) {
    asm volatile("ldmatrix.sync.aligned.m8n8.x4.shared.b16 {%0,%1,%2,%3}, [%4];"
        : "=r"(r[0]), "=r"(r[1]), "=r"(r[2]), "=r"(r[3]) : "r"(a));
}
__device__ __forceinline__ void ldsm2(uint32_t* r, uint32_t a) {
    asm volatile("ldmatrix.sync.aligned.m8n8.x2.shared.b16 {%0,%1}, [%2];"
        : "=r"(r[0]), "=r"(r[1]) : "r"(a));
}
__device__ __forceinline__ void ldsm2t(uint32_t* r, uint32_t a) {
    asm volatile("ldmatrix.sync.aligned.m8n8.x2.trans.shared.b16 {%0,%1}, [%2];"
        : "=r"(r[0]), "=r"(r[1]) : "r"(a));
}
__device__ __forceinline__ void mma16816(float* d, const uint32_t* a, const uint32_t* b) {
    asm volatile("mma.sync.aligned.m16n8k16.row.col.f32.bf16.bf16.f32 "
        "{%0,%1,%2,%3}, {%4,%5,%6,%7}, {%8,%9}, {%0,%1,%2,%3};"
        : "+f"(d[0]), "+f"(d[1]), "+f"(d[2]), "+f"(d[3])
        : "r"(a[0]), "r"(a[1]), "r"(a[2]), "r"(a[3]), "r"(b[0]), "r"(b[1]));
}
__device__ __forceinline__ void split2(float a, float b, uint32_t& hi, uint32_t& lo) {
    __nv_bfloat162 h = __float22bfloat162_rn(make_float2(a, b));
    float2 hf = __bfloat1622float2(h);
    __nv_bfloat162 l = __float22bfloat162_rn(make_float2(a - hf.x, b - hf.y));
    hi = *(uint32_t*)&h; lo = *(uint32_t*)&l;
}

// ---------------------------------------------------------------------------
// convert kernels: fp32 -> bf16 hi/lo
// ---------------------------------------------------------------------------
__global__ __launch_bounds__(256) void conv_x_kernel(const float* __restrict__ x)
{
    size_t i = ((size_t)blockIdx.x*256 + threadIdx.x)*4;
    float4 v = *(const float4*)(x + i);
    uint32_t h0, l0, h1, l1;
    split2(v.x, v.y, h0, l0);
    split2(v.z, v.w, h1, l1);
    *(uint2*)(g_xh + i) = make_uint2(h0, h1);
    *(uint2*)(g_xl + i) = make_uint2(l0, l1);
}
__global__ __launch_bounds__(256) void conv_w_kernel(
    const float* __restrict__ Wk, const float* __restrict__ Wq, const float* __restrict__ Wv)
{
    const int w = blockIdx.y;
    const float* W = (w == 0) ? Wq : (w == 1) ? Wk : Wv;
    size_t base = (size_t)w*EMBED*HEAD;
    size_t i = ((size_t)blockIdx.x*256 + threadIdx.x)*4;
    float4 v = *(const float4*)(W + i);
    uint32_t h0, l0, h1, l1;
    split2(v.x, v.y, h0, l0);
    split2(v.z, v.w, h1, l1);
    *(uint2*)(g_wh + base + i) = make_uint2(h0, h1);
    *(uint2*)(g_wl + base + i) = make_uint2(l0, l1);
}

// ---------------------------------------------------------------------------
// zero / normalize
// ---------------------------------------------------------------------------
__global__ __launch_bounds__(256) void zero_kernel(float* __restrict__ out)
{
    int bid = blockIdx.x;
    if (bid < 2048) {
        size_t i = ((size_t)bid*256 + threadIdx.x)*4;
        *(float4*)(out + i) = make_float4(0.f, 0.f, 0.f, 0.f);
    } else {
        size_t i = ((size_t)(bid - 2048)*256 + threadIdx.x)*4;
        *(float4*)(g_l + i) = make_float4(0.f, 0.f, 0.f, 0.f);
    }
}
__global__ __launch_bounds__(256) void norm_kernel(float* __restrict__ out)
{
    size_t i4 = (size_t)blockIdx.x*256 + threadIdx.x;
    int row = (int)(i4 >> 5);
    float inv = 1.f / g_l[row];
    float4 v = *(float4*)(out + i4*4);
    v.x *= inv; v.y *= inv; v.z *= inv; v.w *= inv;
    *(float4*)(out + i4*4) = v;
}

// ---------------------------------------------------------------------------
// Projection GEMM on HMMA (unchanged from R3)
// ---------------------------------------------------------------------------
#define PJ_STAGE 65536
#define PJ_SMEM  (2*PJ_STAGE)

__global__ __launch_bounds__(256, 1) void proj_kernel()
{
    extern __shared__ char sm[];
    const uint32_t smb = smem_u32(sm);
    const int tid = threadIdx.x, wid = tid >> 5, l = tid & 31;
    const int w = blockIdx.y;
    const int row0 = blockIdx.x * 128;

    const __nv_bfloat16* xh = g_xh + (size_t)row0*EMBED;
    const __nv_bfloat16* xl = g_xl + (size_t)row0*EMBED;
    const __nv_bfloat16* wh = g_wh + (size_t)w*EMBED*HEAD;
    const __nv_bfloat16* wl = g_wl + (size_t)w*EMBED*HEAD;

    auto load_stage = [&](int s, int k0) {
        uint32_t sb = smb + s*PJ_STAGE;
        #pragma unroll
        for (int i = 0; i < 4; i++) {
            int f = i*256 + tid;
            int r = f >> 3, c = f & 7;
            uint32_t d = sb + sidx(r, c*16, 128);
            cpa(d,         xh + (size_t)r*EMBED + k0 + c*8);
            cpa(d + 16384, xl + (size_t)r*EMBED + k0 + c*8);
        }
        #pragma unroll
        for (int i = 0; i < 4; i++) {
            int f = i*256 + tid;
            int r = f >> 4, c = f & 15;
            uint32_t d = sb + 32768 + sidx(r, c*16, 256);
            cpa(d,         wh + (size_t)(k0 + r)*HEAD + c*8);
            cpa(d + 16384, wl + (size_t)(k0 + r)*HEAD + c*8);
        }
        CP_COMMIT();
    };

    float acc[16][4];
    #pragma unroll
    for (int n = 0; n < 16; n++)
        #pragma unroll
        for (int j = 0; j < 4; j++) acc[n][j] = 0.f;

    load_stage(0, 0);
    const int rb = wid*16;

    for (int ch = 0; ch < 16; ch++) {
        int cur = ch & 1;
        if (ch + 1 < 16) { load_stage(cur ^ 1, (ch + 1)*64); CP_WAIT1(); }
        else             { CP_WAIT0(); }
        __syncthreads();

        uint32_t sb = smb + cur*PJ_STAGE;
        #pragma unroll
        for (int ks = 0; ks < 4; ks++) {
            uint32_t ah[4], al[4];
            uint32_t aoff = sidx(rb + (l & 15), ks*32 + ((l >> 4) << 4), 128);
            ldsm4(ah, sb + aoff);
            ldsm4(al, sb + 16384 + aoff);
            #pragma unroll
            for (int nt = 0; nt < 16; nt++) {
                uint32_t bh[2], bl2[2];
                uint32_t boff = sidx(ks*16 + (l & 15), nt*16, 256);
                ldsm2t(bh,  sb + 32768 + boff);
                ldsm2t(bl2, sb + 49152 + boff);
                mma16816(acc[nt], ah, bh);
                mma16816(acc[nt], ah, bl2);
                mma16816(acc[nt], al, bh);
            }
        }
        __syncthreads();
    }

    __nv_bfloat16* dh = (w == 0) ? g_qh : (w == 1) ? g_kh : g_vh;
    __nv_bfloat16* dl = (w == 0) ? g_ql : (w == 1) ? g_kl : g_vl;
    const int g0 = row0 + rb + (l >> 2);
    const int cb = (l & 3)*2;
    #pragma unroll
    for (int nt = 0; nt < 16; nt++) {
        uint32_t h, lo;
        split2(acc[nt][0], acc[nt][1], h, lo);
        *(uint32_t*)(dh + (size_t)g0*HEAD + nt*8 + cb) = h;
        *(uint32_t*)(dl + (size_t)g0*HEAD + nt*8 + cb) = lo;
        split2(acc[nt][2], acc[nt][3], h, lo);
        *(uint32_t*)(dh + (size_t)(g0 + 8)*HEAD + nt*8 + cb) = h;
        *(uint32_t*)(dl + (size_t)(g0 + 8)*HEAD + nt*8 + cb) = lo;
    }
}

// ---------------------------------------------------------------------------
// Flash attention: 8 warps (2/SMSP), 64 queries, keys split across warp
// halves, split-KV chunks of 32 k-tiles across CTAs (additive partials).
// smem: QH 16K | QL 16K | 2 x stage{KH,KL,VH,VL each 16K} = 160KB
// ---------------------------------------------------------------------------
#define AT_KV0   32768
#define AT_STAGE 65536
#define AT_SMEM  (AT_KV0 + 2*AT_STAGE)
#define CHUNK    32   // k-tiles per CTA

__global__ __launch_bounds__(256, 1) void attn_kernel(float* __restrict__ out)
{
    const int qt = 63 - blockIdx.x;            // heavy q-tiles first
    const int c  = blockIdx.y;
    const int t0 = c*CHUNK;
    const int t1 = min(t0 + CHUNK, qt + 1);
    if (t0 >= t1) return;

    extern __shared__ char sm[];
    const uint32_t smb = smem_u32(sm);
    const int tid = threadIdx.x, wid = tid >> 5, l = tid & 31;
    const int b   = blockIdx.z;
    const int q0  = qt*64;
    const int wq  = (wid & 3)*16;              // query sub-tile
    const int kh  = wid >> 2;                  // key half (0/1)
    const bool single = (c == 0) && (qt + 1 <= CHUNK);

    // Q tiles (persistent); committed with first KV stage
    {
        const __nv_bfloat16* qh = g_qh + ((size_t)b*SEQ + q0)*HEAD;
        const __nv_bfloat16* ql = g_ql + ((size_t)b*SEQ + q0)*HEAD;
        #pragma unroll
        for (int i = 0; i < 4; i++) {
            int f = i*256 + tid;
            int r = f >> 4, cc = f & 15;
            uint32_t d = smb + sidx(r, cc*16, 256);
            cpa(d,         qh + (size_t)r*HEAD + cc*8);
            cpa(d + 16384, ql + (size_t)r*HEAD + cc*8);
        }
    }

    auto load_kv = [&](int s, int t) {
        uint32_t sb = smb + AT_KV0 + s*AT_STAGE;
        const size_t base = ((size_t)b*SEQ + t*64)*HEAD;
        #pragma unroll
        for (int i = 0; i < 4; i++) {
            int f = i*256 + tid;
            int r = f >> 4, cc = f & 15;
            uint32_t d = sb + sidx(r, cc*16, 256);
            const size_t g = base + (size_t)r*HEAD + cc*8;
            cpa(d,         g_kh + g);
            cpa(d + 16384, g_kl + g);
            cpa(d + 32768, g_vh + g);
            cpa(d + 49152, g_vl + g);
        }
        CP_COMMIT();
    };

    float o[16][4];
    #pragma unroll
    for (int n = 0; n < 16; n++)
        #pragma unroll
        for (int j = 0; j < 4; j++) o[n][j] = 0.f;
    float lsum0 = 0.f, lsum1 = 0.f;

    load_kv(0, t0);

    for (int t = t0; t < t1; t++) {
        int cur = (t - t0) & 1;
        if (t + 1 < t1) { load_kv(cur ^ 1, t + 1); CP_WAIT1(); }
        else            { CP_WAIT0(); }
        __syncthreads();

        uint32_t sb = smb + AT_KV0 + cur*AT_STAGE;

        // ---- scores S[16q x 32k] for this warp's key half ----
        float s[4][4];
        #pragma unroll
        for (int n = 0; n < 4; n++)
            #pragma unroll
            for (int j = 0; j < 4; j++) s[n][j] = 0.f;

        #pragma unroll
        for (int ks = 0; ks < 8; ks++) {
            uint32_t ah[4], al[4];
            uint32_t aoff = sidx(wq + (l & 15), ks*32 + ((l >> 4) << 4), 256);
            ldsm4(ah, smb + aoff);
            ldsm4(al, smb + 16384 + aoff);
            #pragma unroll
            for (int nt = 0; nt < 4; nt++) {
                uint32_t bh[2], bl2[2];
                uint32_t boff = sidx(kh*32 + nt*8 + (l & 7), ks*32 + ((l >> 3) & 1)*16, 256);
                ldsm2(bh,  sb + boff);
                ldsm2(bl2, sb + 16384 + boff);
                mma16816(s[nt], ah, bh);
                mma16816(s[nt], ah, bl2);
                mma16816(s[nt], al, bh);
            }
        }

        // ---- p = exp(s*scale), causal mask on diagonal tile ----
        uint32_t Ph[4][2], Pl[4][2];
        const bool diag = (t == qt);
        const int lq = q0 + wq + (l >> 2);
        #pragma unroll
        for (int nt = 0; nt < 4; nt++) {
            int kc = t*64 + kh*32 + nt*8 + (l & 3)*2;
            float p00 = __expf(s[nt][0]*SCALE);
            float p01 = __expf(s[nt][1]*SCALE);
            float p10 = __expf(s[nt][2]*SCALE);
            float p11 = __expf(s[nt][3]*SCALE);
            if (diag) {
                if (kc     > lq)     p00 = 0.f;
                if (kc + 1 > lq)     p01 = 0.f;
                if (kc     > lq + 8) p10 = 0.f;
                if (kc + 1 > lq + 8) p11 = 0.f;
            }
            lsum0 += p00 + p01;
            lsum1 += p10 + p11;
            split2(p00, p01, Ph[nt][0], Pl[nt][0]);
            split2(p10, p11, Ph[nt][1], Pl[nt][1]);
        }

        // ---- O += P * V over this warp's 32 keys ----
        #pragma unroll
        for (int ks = 0; ks < 2; ks++) {
            uint32_t ahh[4] = {Ph[2*ks][0], Ph[2*ks][1], Ph[2*ks+1][0], Ph[2*ks+1][1]};
            uint32_t all[4] = {Pl[2*ks][0], Pl[2*ks][1], Pl[2*ks+1][0], Pl[2*ks+1][1]};
            #pragma unroll
            for (int nt = 0; nt < 16; nt++) {
                uint32_t bh[2], bl2[2];
                uint32_t boff = sidx(kh*32 + ks*16 + (l & 15), nt*16, 256);
                ldsm2t(bh,  sb + 32768 + boff);
                ldsm2t(bl2, sb + 49152 + boff);
                mma16816(o[nt], ahh, bh);
                mma16816(o[nt], ahh, bl2);
                mma16816(o[nt], all, bh);
            }
        }
        __syncthreads();
    }

    // ---- cross-half reduction via smem (warps w and w+4 share queries) ----
    if (wid >= 4) {
        float* red = (float*)(sm + AT_KV0) + ((size_t)((wid - 4)*32 + l))*64;
        #pragma unroll
        for (int nt = 0; nt < 16; nt++)
            *(float4*)(red + nt*4) = make_float4(o[nt][0], o[nt][1], o[nt][2], o[nt][3]);
        float* lred = (float*)(sm + AT_KV0 + 32768) + ((wid - 4)*32 + l)*2;
        lred[0] = lsum0; lred[1] = lsum1;
    }
    __syncthreads();
    if (wid < 4) {
        float* red = (float*)(sm + AT_KV0) + ((size_t)(wid*32 + l))*64;
        #pragma unroll
        for (int nt = 0; nt < 16; nt++) {
            float4 r = *(float4*)(red + nt*4);
            o[nt][0] += r.x; o[nt][1] += r.y; o[nt][2] += r.z; o[nt][3] += r.w;
        }
        float* lred = (float*)(sm + AT_KV0 + 32768) + (wid*32 + l)*2;
        lsum0 += lred[0]; lsum1 += lred[1];

        lsum0 += __shfl_xor_sync(0xffffffffu, lsum0, 1);
        lsum0 += __shfl_xor_sync(0xffffffffu, lsum0, 2);
        lsum1 += __shfl_xor_sync(0xffffffffu, lsum1, 1);
        lsum1 += __shfl_xor_sync(0xffffffffu, lsum1, 2);

        const int row0g = q0 + wq + (l >> 2);
        const int cb = (l & 3)*2;
        float* og = out + ((size_t)b*SEQ + row0g)*HEAD;

        if (single) {
            #pragma unroll
            for (int nt = 0; nt < 16; nt++) {
                *(float2*)(og + nt*8 + cb) = make_float2(o[nt][0], o[nt][1]);
                *(float2*)(og + (size_t)8*HEAD + nt*8 + cb) = make_float2(o[nt][2], o[nt][3]);
            }
            if ((l & 3) == 0) {
                g_l[b*SEQ + row0g]     = lsum0;
                g_l[b*SEQ + row0g + 8] = lsum1;
            }
        } else {
            #pragma unroll
            for (int nt = 0; nt < 16; nt++) {
                atomicAdd(og + nt*8 + cb,     o[nt][0]);
                atomicAdd(og + nt*8 + cb + 1, o[nt][1]);
                atomicAdd(og + (size_t)8*HEAD + nt*8 + cb,     o[nt][2]);
                atomicAdd(og + (size_t)8*HEAD + nt*8 + cb + 1, o[nt][3]);
            }
            if ((l & 3) == 0) {
                atomicAdd(g_l + b*SEQ + row0g,     lsum0);
                atomicAdd(g_l + b*SEQ + row0g + 8, lsum1);
            }
        }
    }
}

// ---------------------------------------------------------------------------
extern "C" void kernel_launch(void* const* d_in, const int* in_sizes, int n_in,
                              void* d_out, int out_size)
{
    const float* x  = (const float*)d_in[0];
    const float* Wk = (const float*)d_in[1];
    const float* Wq = (const float*)d_in[2];
    const float* Wv = (const float*)d_in[3];
    float* out = (float*)d_out;

    cudaFuncSetAttribute(proj_kernel, cudaFuncAttributeMaxDynamicSharedMemorySize, PJ_SMEM);
    cudaFuncSetAttribute(attn_kernel, cudaFuncAttributeMaxDynamicSharedMemorySize, AT_SMEM);

    zero_kernel<<<2064, 256>>>(out);
    conv_x_kernel<<<BS*EMBED/1024, 256>>>(x);
    conv_w_kernel<<<dim3(EMBED*HEAD/1024, 3), 256>>>(Wk, Wq, Wv);
    proj_kernel<<<dim3(BS/128, 3), 256, PJ_SMEM>>>();
    attn_kernel<<<dim3(64, (SEQ/64 + CHUNK - 1)/CHUNK, BATCH), 256, AT_SMEM>>>(out);
    norm_kernel<<<BS*HEAD/1024, 256>>>(out);
}